// round 13
// baseline (speedup 1.0000x reference)
#include <cuda_runtime.h>
#include <cuda_fp16.h>
#include <cstdint>

// Conditional_encoding: B=1024, T=256, V=32004, D=50, H=64
// Stage 1: GX[layer][v][hd*4+gate] = Wih@emb[v] + bih + bhh (token gate table, L2-resident).
// Stage 2: 147 CTAs x 512 threads, NB=7. Recurrence h@Whh^T on tensor cores
//   (m16n8k16 fp16 hi/lo split, 3 passes, fp32-accurate).
//   ONE barrier/step: warp w owns hidden dims 4w..4w+3 across all 4 gates
//   (ntile0 = {i,f} rows, ntile1 = {g,o} rows); MMA outputs are exchanged through a
//   warp-private smem scratch (STS -> syncwarp -> LDS, conflict-free stride 18),
//   the cell update runs inside the MMA warp, h double-buffered.

typedef unsigned long long ull;

#define NB   7
#define TPB  512
#define GRID 147
#define VOC  32004

__device__ __align__(16) float GXT[2][(size_t)VOC * 256];

__device__ __forceinline__ ull ffma2(ull a, ull b, ull c) {
    ull d;
    asm("fma.rn.f32x2 %0, %1, %2, %3;" : "=l"(d) : "l"(a), "l"(b), "l"(c));
    return d;
}
__device__ __forceinline__ float lo32(ull v) { return __uint_as_float((unsigned)v); }
__device__ __forceinline__ float hi32(ull v) { return __uint_as_float((unsigned)(v >> 32)); }
__device__ __forceinline__ float tanhap(float x) {
    float y;
    asm("tanh.approx.f32 %0, %1;" : "=f"(y) : "f"(x));
    return y;
}
__device__ __forceinline__ float sigm(float x) { return 0.5f * tanhap(0.5f * x) + 0.5f; }

__device__ __forceinline__ void mma16816(float& c0, float& c1, float& c2, float& c3,
                                         unsigned a0, unsigned a1, unsigned a2, unsigned a3,
                                         unsigned b0, unsigned b1) {
    asm volatile("mma.sync.aligned.m16n8k16.row.col.f32.f16.f16.f32 "
                 "{%0,%1,%2,%3}, {%4,%5,%6,%7}, {%8,%9}, {%0,%1,%2,%3};"
                 : "+f"(c0), "+f"(c1), "+f"(c2), "+f"(c3)
                 : "r"(a0), "r"(a1), "r"(a2), "r"(a3), "r"(b0), "r"(b1));
}
__device__ __forceinline__ void ldmat_x4(unsigned& r0, unsigned& r1, unsigned& r2, unsigned& r3,
                                         uint32_t addr) {
    asm volatile("ldmatrix.sync.aligned.m8n8.x4.shared.b16 {%0,%1,%2,%3}, [%4];"
                 : "=r"(r0), "=r"(r1), "=r"(r2), "=r"(r3) : "r"(addr));
}
__device__ __forceinline__ unsigned h2u(__half2 h) { return *reinterpret_cast<unsigned*>(&h); }
__device__ __forceinline__ uint32_t smem_u32(const void* p) {
    return (uint32_t)__cvta_generic_to_shared(p);
}

// ---------------- stage 1: vocab gate-table precompute (4 tokens / iter) ----------------
#define PCT 4
#define PCI 14
#define PCC (PCT * PCI)
#define PCG ((VOC + PCC - 1) / PCC)

__global__ void __launch_bounds__(256)
precompute_gx(const float* __restrict__ emb,
              const float* __restrict__ Wih1, const float* __restrict__ bih1,
              const float* __restrict__ bhh1,
              const float* __restrict__ Wih2, const float* __restrict__ bih2,
              const float* __restrict__ bhh2)
{
    const int layer = blockIdx.y;
    const float* __restrict__ Wih = layer ? Wih2 : Wih1;
    const float* __restrict__ bi  = layer ? bih2 : bih1;
    const float* __restrict__ bh  = layer ? bhh2 : bhh1;
    float* __restrict__ GX = GXT[layer];

    const int tid = threadIdx.x;                  // gate row (gate = tid>>6, hd = tid&63)
    const int sto = (tid & 63) * 4 + (tid >> 6);  // transposed output index
    ull wih[25];
    const ull* wr = reinterpret_cast<const ull*>(Wih + tid * 50);
    #pragma unroll
    for (int k = 0; k < 25; k++) wih[k] = wr[k];
    const float bsum = bi[tid] + bh[tid];

    __shared__ __align__(16) float xb[2][PCT][52];
    const int v0 = blockIdx.x * PCC;
    const int lt = tid / 50, ld = tid % 50;
    const bool lp = tid < PCT * 50;

    if (lp) {
        int v = min(v0 + lt, VOC - 1);
        xb[0][lt][ld] = __ldg(&emb[(size_t)v * 50 + ld]);
    }
    __syncthreads();

    for (int it = 0; it < PCI; it++) {
        const int cur = it & 1;
        const int vb = v0 + it * PCT;
        float pf = 0.f;
        if (lp && it + 1 < PCI) {
            int v = min(vb + PCT + lt, VOC - 1);
            pf = __ldg(&emb[(size_t)v * 50 + ld]);
        }
        ull acc[PCT] = {0ull, 0ull, 0ull, 0ull};
        #pragma unroll
        for (int k = 0; k < 25; k++) {
            #pragma unroll
            for (int t = 0; t < PCT; t++)
                acc[t] = ffma2(wih[k], *reinterpret_cast<const ull*>(&xb[cur][t][k * 2]), acc[t]);
        }
        #pragma unroll
        for (int t = 0; t < PCT; t++) {
            int v = vb + t;
            if (v < VOC) GX[(size_t)v * 256 + sto] = (lo32(acc[t]) + hi32(acc[t])) + bsum;
        }
        if (lp && it + 1 < PCI) xb[cur ^ 1][lt][ld] = pf;
        __syncthreads();
    }
}

// ---------------- stage 2: fused recurrence on tensor cores ----------------
#define HPS 72    // h row stride in halves (144B; 8-row ldmatrix tiles conflict-free)
#define SCS 128   // per-warp scratch floats (rows stride 18, 7 rows used)

struct SmemT {
    __half hhi[2][8][HPS];     // double-buffered fp16 hi of h; row 7 = zero
    __half hlo[2][8][HPS];     // double-buffered fp16 lo of h; row 7 = zero
    float  scr[16][SCS];       // warp-private psum exchange scratch
    float  gh[NB][64];
    float  gc[NB][64];
    float  f1[NB][128];
    int    sidx[NB][256];
};

__device__ __forceinline__ void run_lstm(
    int warp, int lane, int grp, int tig, bool act, int myg,
    const float* __restrict__ gx, const float* __restrict__ Whh,
    SmemT* sm, float& c)
{
    // ---- B fragments: warp w owns Whh rows for hidden dims 4w..4w+3, all gates.
    // ntile tile-col n = grp: gate = nt*2 + (grp>>2), dim = 4w + (grp&3).
    unsigned bhf[2][4][2], blf[2][4][2];
    #pragma unroll
    for (int nt = 0; nt < 2; nt++) {
        const int row = (nt * 2 + (grp >> 2)) * 64 + warp * 4 + (grp & 3);
        #pragma unroll
        for (int kt = 0; kt < 4; kt++) {
            int k = kt * 16 + tig * 2;
            float2 w0 = *reinterpret_cast<const float2*>(&Whh[row * 64 + k]);
            float2 w1 = *reinterpret_cast<const float2*>(&Whh[row * 64 + k + 8]);
            __half2 h0 = __floats2half2_rn(w0.x, w0.y);
            __half2 h1 = __floats2half2_rn(w1.x, w1.y);
            float2 r0 = __half22float2(h0), r1 = __half22float2(h1);
            __half2 l0 = __floats2half2_rn(w0.x - r0.x, w0.y - r0.y);
            __half2 l1 = __floats2half2_rn(w1.x - r1.x, w1.y - r1.y);
            bhf[nt][kt][0] = h2u(h0); bhf[nt][kt][1] = h2u(h1);
            blf[nt][kt][0] = h2u(l0); blf[nt][kt][1] = h2u(l1);
        }
    }

    // ---- ldmatrix lane addressing: tile = lane>>3, row = lane&7 ----
    const int tt = lane >> 3, rr = lane & 7, co = (tt & 1) * 8;
    const uint32_t aA0 = smem_u32((tt < 2) ? (const void*)&sm->hhi[0][rr][co]
                                           : (const void*)&sm->hlo[0][rr][co]);
    const uint32_t aA1 = smem_u32((tt < 2) ? (const void*)&sm->hhi[1][rr][co]
                                           : (const void*)&sm->hlo[1][rr][co]);

    const int j = grp;                       // batch owned by this lane
    const int hd = warp * 4 + tig;           // hidden dim owned by this lane
    float* __restrict__ sc = sm->scr[warp];
    const int sb = 18 * grp;

    // gx for step 0 (gates i,f,g,o of dim hd, one float4)
    float4 g4 = make_float4(0.f, 0.f, 0.f, 0.f);
    if (act)
        g4 = __ldg(reinterpret_cast<const float4*>(gx + (size_t)sm->sidx[j][0] * 256) + hd);

    for (int step = 0; step < 256; step++) {
        const int cur = step & 1;
        const uint32_t ab = cur ? aA1 : aA0;

        // ---- prefetch next step's gx BEFORE the MMA burst ----
        float4 n4 = make_float4(0.f, 0.f, 0.f, 0.f);
        if (act && step < 255)
            n4 = __ldg(reinterpret_cast<const float4*>(
                     gx + (size_t)sm->sidx[j][step + 1] * 256) + hd);

        // ---- A fragments: 4 ldmatrix.x4 (hi k0-7, hi k8-15, lo k0-7, lo k8-15) ----
        unsigned A0h[4], A2h[4], A0l[4], A2l[4];
        #pragma unroll
        for (int kt = 0; kt < 4; kt++)
            ldmat_x4(A0h[kt], A2h[kt], A0l[kt], A2l[kt], ab + kt * 32);

        // ---- 24 HMMA: 2 ntiles x 2 k-half chains x 3 precision passes ----
        float cA0 = 0.f, cA1 = 0.f, cA2 = 0.f, cA3 = 0.f;
        float cB0 = 0.f, cB1 = 0.f, cB2 = 0.f, cB3 = 0.f;
        float cC0 = 0.f, cC1 = 0.f, cC2 = 0.f, cC3 = 0.f;
        float cD0 = 0.f, cD1 = 0.f, cD2 = 0.f, cD3 = 0.f;
        #pragma unroll
        for (int kh = 0; kh < 2; kh++) {
            float &x0 = kh ? cB0 : cA0, &x1 = kh ? cB1 : cA1,
                  &x2 = kh ? cB2 : cA2, &x3 = kh ? cB3 : cA3;
            float &y0 = kh ? cD0 : cC0, &y1 = kh ? cD1 : cC1,
                  &y2 = kh ? cD2 : cC2, &y3 = kh ? cD3 : cC3;
            #pragma unroll
            for (int kk = 0; kk < 2; kk++) {
                int kt = kh * 2 + kk;
                mma16816(x0, x1, x2, x3, A0h[kt], 0u, A2h[kt], 0u, bhf[0][kt][0], bhf[0][kt][1]);
                mma16816(y0, y1, y2, y3, A0h[kt], 0u, A2h[kt], 0u, bhf[1][kt][0], bhf[1][kt][1]);
                mma16816(x0, x1, x2, x3, A0l[kt], 0u, A2l[kt], 0u, bhf[0][kt][0], bhf[0][kt][1]);
                mma16816(y0, y1, y2, y3, A0l[kt], 0u, A2l[kt], 0u, bhf[1][kt][0], bhf[1][kt][1]);
                mma16816(x0, x1, x2, x3, A0h[kt], 0u, A2h[kt], 0u, blf[0][kt][0], blf[0][kt][1]);
                mma16816(y0, y1, y2, y3, A0h[kt], 0u, A2h[kt], 0u, blf[1][kt][0], blf[1][kt][1]);
            }
        }

        // ---- in-warp psum exchange via scratch (no CTA barrier) ----
        if (act) {
            *reinterpret_cast<float2*>(&sc[sb + 2 * tig])     = make_float2(cA0 + cB0, cA1 + cB1);
            *reinterpret_cast<float2*>(&sc[sb + 8 + 2 * tig]) = make_float2(cC0 + cD0, cC1 + cD1);
        }
        __syncwarp();

        // ---- cell update on the owning lane: unit (j, hd = 4w + tig) ----
        if (act) {
            float iv = sc[sb + tig]      + g4.x;   // ntile0 col tig   -> gate i
            float fv = sc[sb + 4 + tig]  + g4.y;   // ntile0 col 4+tig -> gate f
            float gv = sc[sb + 8 + tig]  + g4.z;   // ntile1 col tig   -> gate g
            float ov = sc[sb + 12 + tig] + g4.w;   // ntile1 col 4+tig -> gate o
            c = sigm(fv) * c + sigm(iv) * tanhap(gv);
            float h = sigm(ov) * tanhap(c);
            __half hh = __float2half_rn(h);
            sm->hhi[cur ^ 1][j][hd] = hh;
            sm->hlo[cur ^ 1][j][hd] = __float2half_rn(h - __half2float(hh));
            if (step == myg) { sm->gh[j][hd] = h; sm->gc[j][hd] = c; }
            g4 = n4;
        }
        __syncthreads();   // h[next] visible to all warps' ldmatrix
    }
}

__global__ void __launch_bounds__(TPB, 1)
cond_enc_kernel(const int* __restrict__ s1, const int* __restrict__ s2,
                const int* __restrict__ l1, const int* __restrict__ l2,
                const float* __restrict__ Whh1, const float* __restrict__ Whh2,
                const float* __restrict__ Wl1, const float* __restrict__ bl1,
                const float* __restrict__ Wl2, const float* __restrict__ bl2,
                float* __restrict__ out)
{
    __shared__ SmemT sm;
    const int tid  = threadIdx.x;
    const int base = blockIdx.x * NB;
    const int warp = tid >> 5, lane = tid & 31;
    const int grp = lane >> 2, tig = lane & 3;
    const bool act = grp < NB;
    const int j = grp, hd = warp * 4 + tig;
    const int bj = act ? min(base + j, 1023) : 0;

    // ---------- zero both h buffers (incl. padding), load sentence1 ----------
    {
        unsigned* hz = reinterpret_cast<unsigned*>(sm.hhi);
        unsigned* lz = reinterpret_cast<unsigned*>(sm.hlo);
        for (int i = tid; i < 2 * 8 * HPS / 2; i += TPB) { hz[i] = 0u; lz[i] = 0u; }
    }
    for (int i = tid; i < NB * 256; i += TPB) {
        int jj = i >> 8, t = i & 255;
        int b = min(base + jj, 1023);
        sm.sidx[jj][t] = s1[b * 256 + t];
    }
    int myg = act ? l1[bj * 64 + hd] : -1;
    __syncthreads();

    float c = 0.f;
    run_lstm(warp, lane, grp, tig, act, myg, GXT[0], Whh1, &sm, c);

    // ---------- capture gathered state, switch to sentence2 ----------
    float hinit = 0.f;
    if (act) { hinit = sm.gh[j][hd]; c = sm.gc[j][hd]; }
    __syncthreads();
    for (int i = tid; i < NB * 256; i += TPB) {
        int jj = i >> 8, t = i & 255;
        int b = min(base + jj, 1023);
        sm.sidx[jj][t] = s2[b * 256 + t];
    }
    if (act) {
        myg = l2[bj * 64 + hd];
        __half hh = __float2half_rn(hinit);
        sm.hhi[0][j][hd] = hh;
        sm.hlo[0][j][hd] = __float2half_rn(hinit - __half2float(hh));
    }
    __syncthreads();

    run_lstm(warp, lane, grp, tig, act, myg, GXT[1], Whh2, &sm, c);

    // ---------- FC head ----------
    for (int u = tid; u < NB * 128; u += TPB) {
        int jj = u >> 7, f = u & 127;
        const float* w = Wl1 + f * 64;
        float a = bl1[f];
        #pragma unroll
        for (int k = 0; k < 64; k++) a += w[k] * sm.gh[jj][k];
        sm.f1[jj][f] = tanhap(a);
    }
    __syncthreads();
    if (tid < NB * 4) {
        int jj = tid >> 2, o = tid & 3;
        const float* w = Wl2 + o * 128;
        float a = bl2[o];
        #pragma unroll 16
        for (int k = 0; k < 128; k++) a += w[k] * sm.f1[jj][k];
        int b = base + jj;
        if (b < 1024) out[b * 4 + o] = a;
    }
}

extern "C" void kernel_launch(void* const* d_in, const int* in_sizes, int n_in,
                              void* d_out, int out_size)
{
    // 0 s1, 1 s2, 2 s1_len, 3 s2_len, 4 s1_s, 5 s2_s, 6 emb,
    // 7 Wih1, 8 Whh1, 9 bih1, 10 bhh1, 11 Wih2, 12 Whh2, 13 bih2, 14 bhh2,
    // 15 Wl1, 16 bl1, 17 Wl2, 18 bl2
    precompute_gx<<<dim3(PCG, 2), 256>>>(
        (const float*)d_in[6],
        (const float*)d_in[7], (const float*)d_in[9], (const float*)d_in[10],
        (const float*)d_in[11], (const float*)d_in[13], (const float*)d_in[14]);

    cond_enc_kernel<<<GRID, TPB>>>(
        (const int*)d_in[0], (const int*)d_in[1],
        (const int*)d_in[2], (const int*)d_in[3],
        (const float*)d_in[8], (const float*)d_in[12],
        (const float*)d_in[15], (const float*)d_in[16],
        (const float*)d_in[17], (const float*)d_in[18],
        (float*)d_out);
}

// round 14
// speedup vs baseline: 1.9519x; 1.9519x over previous
#include <cuda_runtime.h>
#include <cuda_fp16.h>
#include <cstdint>

// Conditional_encoding: B=1024, T=256, V=32004, D=50, H=64
// Stage 1: GX[layer][v][hd*4+gate] = Wih@emb[v] + bih + bhh (token gate table, L2-resident).
// Stage 2: 147 CTAs x 512 threads, NB=7 (R9 two-phase skeleton: MMA phase / gate phase).
//   Recurrence h@Whh^T on tensor cores, m16n8k16.
//   M-rows 0-7 = h_hi (batches 0-6 + zero), rows 8-15 = h_lo of the same batches.
//   TWO passes (xB_hi, xB_lo) accumulate in place -> 16 HMMA/warp/step; psum for
//   batch j = c0 (row j, hi part) + c2 (row j+8, lo part) within the same lane.
//   This computes the full (Ah+Al)(Bh+Bl) product in fp32 (more accurate than 3-pass).

typedef unsigned long long ull;

#define NB   7
#define TPB  512
#define GRID 147
#define VOC  32004

__device__ __align__(16) float GXT[2][(size_t)VOC * 256];

__device__ __forceinline__ ull ffma2(ull a, ull b, ull c) {
    ull d;
    asm("fma.rn.f32x2 %0, %1, %2, %3;" : "=l"(d) : "l"(a), "l"(b), "l"(c));
    return d;
}
__device__ __forceinline__ float lo32(ull v) { return __uint_as_float((unsigned)v); }
__device__ __forceinline__ float hi32(ull v) { return __uint_as_float((unsigned)(v >> 32)); }
__device__ __forceinline__ float tanhap(float x) {
    float y;
    asm("tanh.approx.f32 %0, %1;" : "=f"(y) : "f"(x));
    return y;
}
__device__ __forceinline__ float sigm(float x) { return 0.5f * tanhap(0.5f * x) + 0.5f; }

__device__ __forceinline__ void mma16816(float& c0, float& c1, float& c2, float& c3,
                                         unsigned a0, unsigned a1, unsigned a2, unsigned a3,
                                         unsigned b0, unsigned b1) {
    asm volatile("mma.sync.aligned.m16n8k16.row.col.f32.f16.f16.f32 "
                 "{%0,%1,%2,%3}, {%4,%5,%6,%7}, {%8,%9}, {%0,%1,%2,%3};"
                 : "+f"(c0), "+f"(c1), "+f"(c2), "+f"(c3)
                 : "r"(a0), "r"(a1), "r"(a2), "r"(a3), "r"(b0), "r"(b1));
}
__device__ __forceinline__ void ldmat_x4(unsigned& r0, unsigned& r1, unsigned& r2, unsigned& r3,
                                         uint32_t addr) {
    asm volatile("ldmatrix.sync.aligned.m8n8.x4.shared.b16 {%0,%1,%2,%3}, [%4];"
                 : "=r"(r0), "=r"(r1), "=r"(r2), "=r"(r3) : "r"(addr));
}
__device__ __forceinline__ unsigned h2u(__half2 h) { return *reinterpret_cast<unsigned*>(&h); }
__device__ __forceinline__ uint32_t smem_u32(const void* p) {
    return (uint32_t)__cvta_generic_to_shared(p);
}

// ---------------- stage 1: vocab gate-table precompute (4 tokens / iter) ----------------
#define PCT 4
#define PCI 14
#define PCC (PCT * PCI)
#define PCG ((VOC + PCC - 1) / PCC)

__global__ void __launch_bounds__(256)
precompute_gx(const float* __restrict__ emb,
              const float* __restrict__ Wih1, const float* __restrict__ bih1,
              const float* __restrict__ bhh1,
              const float* __restrict__ Wih2, const float* __restrict__ bih2,
              const float* __restrict__ bhh2)
{
    const int layer = blockIdx.y;
    const float* __restrict__ Wih = layer ? Wih2 : Wih1;
    const float* __restrict__ bi  = layer ? bih2 : bih1;
    const float* __restrict__ bh  = layer ? bhh2 : bhh1;
    float* __restrict__ GX = GXT[layer];

    const int tid = threadIdx.x;                  // gate row (gate = tid>>6, hd = tid&63)
    const int sto = (tid & 63) * 4 + (tid >> 6);  // transposed output index
    ull wih[25];
    const ull* wr = reinterpret_cast<const ull*>(Wih + tid * 50);
    #pragma unroll
    for (int k = 0; k < 25; k++) wih[k] = wr[k];
    const float bsum = bi[tid] + bh[tid];

    __shared__ __align__(16) float xb[2][PCT][52];
    const int v0 = blockIdx.x * PCC;
    const int lt = tid / 50, ld = tid % 50;
    const bool lp = tid < PCT * 50;

    if (lp) {
        int v = min(v0 + lt, VOC - 1);
        xb[0][lt][ld] = __ldg(&emb[(size_t)v * 50 + ld]);
    }
    __syncthreads();

    for (int it = 0; it < PCI; it++) {
        const int cur = it & 1;
        const int vb = v0 + it * PCT;
        float pf = 0.f;
        if (lp && it + 1 < PCI) {
            int v = min(vb + PCT + lt, VOC - 1);
            pf = __ldg(&emb[(size_t)v * 50 + ld]);
        }
        ull acc[PCT] = {0ull, 0ull, 0ull, 0ull};
        #pragma unroll
        for (int k = 0; k < 25; k++) {
            #pragma unroll
            for (int t = 0; t < PCT; t++)
                acc[t] = ffma2(wih[k], *reinterpret_cast<const ull*>(&xb[cur][t][k * 2]), acc[t]);
        }
        #pragma unroll
        for (int t = 0; t < PCT; t++) {
            int v = vb + t;
            if (v < VOC) GX[(size_t)v * 256 + sto] = (lo32(acc[t]) + hi32(acc[t])) + bsum;
        }
        if (lp && it + 1 < PCI) xb[cur ^ 1][lt][ld] = pf;
        __syncthreads();
    }
}

// ---------------- stage 2: fused recurrence on tensor cores ----------------
#define HPS 72    // h row stride in halves (144B; 8-row ldmatrix tiles conflict-free)
#define PSS 258

struct SmemT {
    __half hhi[2][8][HPS];     // double-buffered fp16 hi of h; row 7 = zero
    __half hlo[2][8][HPS];     // double-buffered fp16 lo of h; row 7 = zero
    float  psum[NB][PSS];
    float  gh[NB][64];
    float  gc[NB][64];
    float  f1[NB][128];
    int    sidx[NB][256];
};

__device__ __forceinline__ void run_lstm(
    int warp, int lane, int grp, int tig, bool gu, int j, int hd, int myg,
    const float* __restrict__ gx, const float* __restrict__ Whh,
    SmemT* sm, float& c)
{
    // ---- B fragments: row n = warp*16 + nt*8 + grp, hi/lo split ----
    unsigned bhf[2][4][2], blf[2][4][2];
    #pragma unroll
    for (int nt = 0; nt < 2; nt++) {
        const int n = warp * 16 + nt * 8 + grp;
        #pragma unroll
        for (int kt = 0; kt < 4; kt++) {
            int k = kt * 16 + tig * 2;
            float2 w0 = *reinterpret_cast<const float2*>(&Whh[n * 64 + k]);
            float2 w1 = *reinterpret_cast<const float2*>(&Whh[n * 64 + k + 8]);
            __half2 h0 = __floats2half2_rn(w0.x, w0.y);
            __half2 h1 = __floats2half2_rn(w1.x, w1.y);
            float2 r0 = __half22float2(h0), r1 = __half22float2(h1);
            __half2 l0 = __floats2half2_rn(w0.x - r0.x, w0.y - r0.y);
            __half2 l1 = __floats2half2_rn(w1.x - r1.x, w1.y - r1.y);
            bhf[nt][kt][0] = h2u(h0); bhf[nt][kt][1] = h2u(h1);
            blf[nt][kt][0] = h2u(l0); blf[nt][kt][1] = h2u(l1);
        }
    }

    // ---- ldmatrix lane addressing: tile = lane>>3, row = lane&7 ----
    const int tt = lane >> 3, rr = lane & 7, co = (tt & 1) * 8;
    const uint32_t aA0 = smem_u32((tt < 2) ? (const void*)&sm->hhi[0][rr][co]
                                           : (const void*)&sm->hlo[0][rr][co]);
    const uint32_t aA1 = smem_u32((tt < 2) ? (const void*)&sm->hhi[1][rr][co]
                                           : (const void*)&sm->hlo[1][rr][co]);

    // gx for step 0 (one float4 per gate-unit thread)
    float4 g4 = make_float4(0.f, 0.f, 0.f, 0.f);
    if (gu)
        g4 = __ldg(reinterpret_cast<const float4*>(gx + (size_t)sm->sidx[j][0] * 256) + hd);

    for (int step = 0; step < 256; step++) {
        const int cur = step & 1;
        const uint32_t ab = cur ? aA1 : aA0;

        // ---- prefetch next step's gx BEFORE the MMA burst (latency hidden) ----
        float4 n4 = make_float4(0.f, 0.f, 0.f, 0.f);
        if (gu && step < 255)
            n4 = __ldg(reinterpret_cast<const float4*>(
                     gx + (size_t)sm->sidx[j][step + 1] * 256) + hd);

        // ---- A fragments: 4 ldmatrix.x4 (hi k0-7, hi k8-15, lo k0-7, lo k8-15) ----
        unsigned A0h[4], A2h[4], A0l[4], A2l[4];
        #pragma unroll
        for (int kt = 0; kt < 4; kt++)
            ldmat_x4(A0h[kt], A2h[kt], A0l[kt], A2l[kt], ab + kt * 32);

        // ---- 16 HMMA: rows 0-7 = h_hi, rows 8-15 = h_lo; passes x B_hi and x B_lo
        //      accumulate in place. 4 chains = 2 ntiles x 2 k-halves.
        float cA0 = 0.f, cA1 = 0.f, cA2 = 0.f, cA3 = 0.f;
        float cB0 = 0.f, cB1 = 0.f, cB2 = 0.f, cB3 = 0.f;
        float cC0 = 0.f, cC1 = 0.f, cC2 = 0.f, cC3 = 0.f;
        float cD0 = 0.f, cD1 = 0.f, cD2 = 0.f, cD3 = 0.f;
        #pragma unroll
        for (int kh = 0; kh < 2; kh++) {
            float &x0 = kh ? cB0 : cA0, &x1 = kh ? cB1 : cA1,
                  &x2 = kh ? cB2 : cA2, &x3 = kh ? cB3 : cA3;
            float &y0 = kh ? cD0 : cC0, &y1 = kh ? cD1 : cC1,
                  &y2 = kh ? cD2 : cC2, &y3 = kh ? cD3 : cC3;
            #pragma unroll
            for (int kk = 0; kk < 2; kk++) {
                int kt = kh * 2 + kk;
                mma16816(x0, x1, x2, x3, A0h[kt], A0l[kt], A2h[kt], A2l[kt],
                         bhf[0][kt][0], bhf[0][kt][1]);
                mma16816(x0, x1, x2, x3, A0h[kt], A0l[kt], A2h[kt], A2l[kt],
                         blf[0][kt][0], blf[0][kt][1]);
                mma16816(y0, y1, y2, y3, A0h[kt], A0l[kt], A2h[kt], A2l[kt],
                         bhf[1][kt][0], bhf[1][kt][1]);
                mma16816(y0, y1, y2, y3, A0h[kt], A0l[kt], A2h[kt], A2l[kt],
                         blf[1][kt][0], blf[1][kt][1]);
            }
        }
        if (grp < NB) {
            int col = warp * 16 + tig * 2;
            // batch j contribution = row j (hi, c0/c1) + row j+8 (lo, c2/c3)
            *reinterpret_cast<float2*>(&sm->psum[grp][col]) =
                make_float2((cA0 + cA2) + (cB0 + cB2), (cA1 + cA3) + (cB1 + cB3));
            *reinterpret_cast<float2*>(&sm->psum[grp][col + 8]) =
                make_float2((cC0 + cC2) + (cD0 + cD2), (cC1 + cC3) + (cD1 + cD3));
        }
        __syncthreads();

        // ---- gate phase (threads 0..447), one unit each ----
        if (gu) {
            float gi = sm->psum[j][hd]        + g4.x;
            float gf = sm->psum[j][64 + hd]   + g4.y;
            float gg = sm->psum[j][128 + hd]  + g4.z;
            float go = sm->psum[j][192 + hd]  + g4.w;
            c = sigm(gf) * c + sigm(gi) * tanhap(gg);
            float h = sigm(go) * tanhap(c);
            __half hh = __float2half_rn(h);
            sm->hhi[cur ^ 1][j][hd] = hh;
            sm->hlo[cur ^ 1][j][hd] = __float2half_rn(h - __half2float(hh));
            if (step == myg) { sm->gh[j][hd] = h; sm->gc[j][hd] = c; }
            g4 = n4;
        }
        __syncthreads();
    }
}

__global__ void __launch_bounds__(TPB, 1)
cond_enc_kernel(const int* __restrict__ s1, const int* __restrict__ s2,
                const int* __restrict__ l1, const int* __restrict__ l2,
                const float* __restrict__ Whh1, const float* __restrict__ Whh2,
                const float* __restrict__ Wl1, const float* __restrict__ bl1,
                const float* __restrict__ Wl2, const float* __restrict__ bl2,
                float* __restrict__ out)
{
    __shared__ SmemT sm;
    const int tid  = threadIdx.x;
    const int base = blockIdx.x * NB;
    const int warp = tid >> 5, lane = tid & 31;
    const int grp = lane >> 2, tig = lane & 3;
    const bool gu = tid < NB * 64;
    const int j = tid >> 6, hd = tid & 63;
    const int bj = gu ? min(base + j, 1023) : 0;

    // ---------- zero both h buffers (incl. padding row 7), load sentence1 ----------
    {
        unsigned* hz = reinterpret_cast<unsigned*>(sm.hhi);
        unsigned* lz = reinterpret_cast<unsigned*>(sm.hlo);
        for (int i = tid; i < 2 * 8 * HPS / 2; i += TPB) { hz[i] = 0u; lz[i] = 0u; }
    }
    for (int i = tid; i < NB * 256; i += TPB) {
        int jj = i >> 8, t = i & 255;
        int b = min(base + jj, 1023);
        sm.sidx[jj][t] = s1[b * 256 + t];
    }
    int myg = gu ? l1[bj * 64 + hd] : -1;
    __syncthreads();

    float c = 0.f;
    run_lstm(warp, lane, grp, tig, gu, j, hd, myg, GXT[0], Whh1, &sm, c);

    // ---------- capture gathered state, switch to sentence2 ----------
    float hinit = 0.f;
    if (gu) { hinit = sm.gh[j][hd]; c = sm.gc[j][hd]; }
    __syncthreads();
    for (int i = tid; i < NB * 256; i += TPB) {
        int jj = i >> 8, t = i & 255;
        int b = min(base + jj, 1023);
        sm.sidx[jj][t] = s2[b * 256 + t];
    }
    if (gu) {
        myg = l2[bj * 64 + hd];
        __half hh = __float2half_rn(hinit);
        sm.hhi[0][j][hd] = hh;
        sm.hlo[0][j][hd] = __float2half_rn(hinit - __half2float(hh));
    }
    __syncthreads();

    run_lstm(warp, lane, grp, tig, gu, j, hd, myg, GXT[1], Whh2, &sm, c);

    // ---------- FC head ----------
    for (int u = tid; u < NB * 128; u += TPB) {
        int jj = u >> 7, f = u & 127;
        const float* w = Wl1 + f * 64;
        float a = bl1[f];
        #pragma unroll
        for (int k = 0; k < 64; k++) a += w[k] * sm.gh[jj][k];
        sm.f1[jj][f] = tanhap(a);
    }
    __syncthreads();
    if (tid < NB * 4) {
        int jj = tid >> 2, o = tid & 3;
        const float* w = Wl2 + o * 128;
        float a = bl2[o];
        #pragma unroll 16
        for (int k = 0; k < 128; k++) a += w[k] * sm.f1[jj][k];
        int b = base + jj;
        if (b < 1024) out[b * 4 + o] = a;
    }
}

extern "C" void kernel_launch(void* const* d_in, const int* in_sizes, int n_in,
                              void* d_out, int out_size)
{
    // 0 s1, 1 s2, 2 s1_len, 3 s2_len, 4 s1_s, 5 s2_s, 6 emb,
    // 7 Wih1, 8 Whh1, 9 bih1, 10 bhh1, 11 Wih2, 12 Whh2, 13 bih2, 14 bhh2,
    // 15 Wl1, 16 bl1, 17 Wl2, 18 bl2
    precompute_gx<<<dim3(PCG, 2), 256>>>(
        (const float*)d_in[6],
        (const float*)d_in[7], (const float*)d_in[9], (const float*)d_in[10],
        (const float*)d_in[11], (const float*)d_in[13], (const float*)d_in[14]);

    cond_enc_kernel<<<GRID, TPB>>>(
        (const int*)d_in[0], (const int*)d_in[1],
        (const int*)d_in[2], (const int*)d_in[3],
        (const float*)d_in[8], (const float*)d_in[12],
        (const float*)d_in[15], (const float*)d_in[16],
        (const float*)d_in[17], (const float*)d_in[18],
        (float*)d_out);
}